// round 2
// baseline (speedup 1.0000x reference)
#include <cuda_runtime.h>
#include <cuda_bf16.h>

// TopKPool split into 2 kernels:
//   K1: masked linear scores (streams 201 MB of embeddings) — 512 blocks for full SM coverage
//   K2: top-k=8 selection + indicator weights + mean pooling
// Output layout: [pooled (B*D) | attn_weights (B*K)], fp32.

#define NEG_INF (-1e30f)
#define SENTINEL (-2e30f)

constexpr int Bv = 128;
constexpr int Kv = 512;
constexpr int Dv = 768;
constexpr int MAX_TOPK = 64;

constexpr int SPLIT   = 4;           // K-segments per batch row
constexpr int KSEG    = Kv / SPLIT;  // 128 rows per block
constexpr int T1      = 256;         // 8 warps
constexpr int T2      = 512;         // 16 warps

__device__ float g_scores[Bv * Kv];  // 256 KB scratch (allowed: static device global)

// ---------------- K1: scoring ----------------
__global__ __launch_bounds__(T1)
void score_kernel(const float* __restrict__ emb,
                  const int*   __restrict__ mask,
                  const float* __restrict__ w,
                  const float* __restrict__ bias)
{
    __shared__ __align__(16) float s_w[Dv];

    const int tid  = threadIdx.x;
    const int lane = tid & 31;
    const int wid  = tid >> 5;                  // 0..7

    for (int i = tid; i < Dv; i += T1) s_w[i] = w[i];
    __syncthreads();

    const int b   = blockIdx.x / SPLIT;
    const int seg = blockIdx.x % SPLIT;
    const int k0  = seg * KSEG;

    const float bval = bias[0];
    const float* eb  = emb + (size_t)b * Kv * Dv;
    const float4* wv = (const float4*)s_w;

    // 8 warps x 8 iterations x 2 rows = 128 rows per block
    for (int kk = wid; kk < KSEG / 2; kk += 8) {
        const int ka = k0 + kk;
        const int kb = k0 + kk + KSEG / 2;
        const float4* ra = (const float4*)(eb + (size_t)ka * Dv);
        const float4* rb = (const float4*)(eb + (size_t)kb * Dv);

        float acc_a = 0.f, acc_b = 0.f;
        #pragma unroll
        for (int j = 0; j < 6; j++) {
            float4 ea = __ldcs(&ra[j * 32 + lane]);   // streaming: don't pollute L2
            float4 eb4= __ldcs(&rb[j * 32 + lane]);
            float4 ww = wv[j * 32 + lane];
            acc_a += ea.x * ww.x + ea.y * ww.y + ea.z * ww.z + ea.w * ww.w;
            acc_b += eb4.x* ww.x + eb4.y* ww.y + eb4.z* ww.z + eb4.w* ww.w;
        }
        #pragma unroll
        for (int off = 16; off; off >>= 1) {
            acc_a += __shfl_xor_sync(0xFFFFFFFFu, acc_a, off);
            acc_b += __shfl_xor_sync(0xFFFFFFFFu, acc_b, off);
        }
        if (lane == 0) {
            float sa = acc_a + bval;
            float sb = acc_b + bval;
            if (mask[(size_t)b * Kv + ka] == 0) sa = NEG_INF;
            if (mask[(size_t)b * Kv + kb] == 0) sb = NEG_INF;
            g_scores[(size_t)b * Kv + ka] = sa;
            g_scores[(size_t)b * Kv + kb] = sb;
        }
    }
}

// ---------------- K2: top-k + pooling ----------------
__global__ __launch_bounds__(T2)
void topk_pool_kernel(const float* __restrict__ emb,
                      const int*   __restrict__ topk,
                      float*       __restrict__ out)
{
    __shared__ float s_sc[Kv];
    __shared__ float s_rv[16];
    __shared__ int   s_ri[16];
    __shared__ int   s_top[MAX_TOPK];

    const int b    = blockIdx.x;
    const int tid  = threadIdx.x;
    const int lane = tid & 31;
    const int wid  = tid >> 5;                  // 0..15

    s_sc[tid] = g_scores[(size_t)b * Kv + tid];
    __syncthreads();

    int ksel = topk[0];
    if (ksel > Kv) ksel = Kv;
    if (ksel < 1)  ksel = 1;
    if (ksel > MAX_TOPK) ksel = MAX_TOPK;

    float* out_pool = out;                      // (B, D)
    float* out_attn = out + (size_t)Bv * Dv;    // (B, K)

    // zero this row's attn weights (d_out is poisoned)
    out_attn[(size_t)b * Kv + tid] = 0.f;

    // top-k via ksel parallel argmax passes
    for (int m = 0; m < ksel; m++) {
        float v   = s_sc[tid];
        int   idx = tid;
        #pragma unroll
        for (int off = 16; off; off >>= 1) {
            float v2 = __shfl_xor_sync(0xFFFFFFFFu, v, off);
            int   i2 = __shfl_xor_sync(0xFFFFFFFFu, idx, off);
            if (v2 > v || (v2 == v && i2 < idx)) { v = v2; idx = i2; }
        }
        if (lane == 0) { s_rv[wid] = v; s_ri[wid] = idx; }
        __syncthreads();
        if (wid == 0) {
            float v3 = (lane < 16) ? s_rv[lane] : SENTINEL;
            int   i3 = (lane < 16) ? s_ri[lane] : Kv;
            #pragma unroll
            for (int off = 8; off; off >>= 1) {
                float v2 = __shfl_xor_sync(0xFFFFFFFFu, v3, off);
                int   i2 = __shfl_xor_sync(0xFFFFFFFFu, i3, off);
                if (v2 > v3 || (v2 == v3 && i2 < i3)) { v3 = v2; i3 = i2; }
            }
            if (lane == 0) {
                s_top[m]   = i3;
                s_sc[i3]   = SENTINEL;          // knock out for next pass
            }
        }
        __syncthreads();
    }

    const float inv = 1.f / (float)ksel;
    if (tid < ksel)
        out_attn[(size_t)b * Kv + s_top[tid]] = inv;

    const float* eb = emb + (size_t)b * Kv * Dv;
    for (int c = tid; c < Dv; c += T2) {
        float sum = 0.f;
        #pragma unroll 4
        for (int m = 0; m < ksel; m++)
            sum += __ldg(&eb[(size_t)s_top[m] * Dv + c]);
        out_pool[(size_t)b * Dv + c] = sum * inv;
    }
}

extern "C" void kernel_launch(void* const* d_in, const int* in_sizes, int n_in,
                              void* d_out, int out_size)
{
    const float* emb  = (const float*)d_in[0];
    const int*   mask = (const int*)  d_in[1];
    const float* w    = (const float*)d_in[2];
    const float* bias = (const float*)d_in[3];
    const int*   topk = (const int*)  d_in[4];
    float*       out  = (float*)d_out;
    (void)in_sizes; (void)n_in; (void)out_size;

    score_kernel<<<Bv * SPLIT, T1>>>(emb, mask, w, bias);
    topk_pool_kernel<<<Bv, T2>>>(emb, topk, out);
}

// round 3
// speedup vs baseline: 1.0491x; 1.0491x over previous
#include <cuda_runtime.h>
#include <cuda_bf16.h>

// TopKPool split into 2 kernels:
//   K1: masked linear scores (streams 201 MB of embeddings) — 512 blocks, 6.05 TB/s measured
//   K2: top-k selection in one warp's registers (no block barriers in the loop) + vectorized pooling
// Output layout: [pooled (B*D) | attn_weights (B*K)], fp32.

#define NEG_INF (-1e30f)
#define SENTINEL (-2e30f)

constexpr int Bv = 128;
constexpr int Kv = 512;
constexpr int Dv = 768;
constexpr int D4 = Dv / 4;           // 192 float4 per row
constexpr int MAX_TOPK = 64;

constexpr int SPLIT = 4;             // K-segments per batch row
constexpr int KSEG  = Kv / SPLIT;    // 128 rows per block
constexpr int T1    = 256;           // 8 warps
constexpr int T2    = 256;           // 8 warps

__device__ float g_scores[Bv * Kv];  // 256 KB scratch (static device global)

// ---------------- K1: scoring (unchanged from R2 — 6.05 TB/s) ----------------
__global__ __launch_bounds__(T1)
void score_kernel(const float* __restrict__ emb,
                  const int*   __restrict__ mask,
                  const float* __restrict__ w,
                  const float* __restrict__ bias)
{
    __shared__ __align__(16) float s_w[Dv];

    const int tid  = threadIdx.x;
    const int lane = tid & 31;
    const int wid  = tid >> 5;

    for (int i = tid; i < Dv; i += T1) s_w[i] = w[i];
    __syncthreads();

    const int b   = blockIdx.x / SPLIT;
    const int seg = blockIdx.x % SPLIT;
    const int k0  = seg * KSEG;

    const float bval = bias[0];
    const float* eb  = emb + (size_t)b * Kv * Dv;
    const float4* wv = (const float4*)s_w;

    for (int kk = wid; kk < KSEG / 2; kk += 8) {
        const int ka = k0 + kk;
        const int kb = k0 + kk + KSEG / 2;
        const float4* ra = (const float4*)(eb + (size_t)ka * Dv);
        const float4* rb = (const float4*)(eb + (size_t)kb * Dv);

        float acc_a = 0.f, acc_b = 0.f;
        #pragma unroll
        for (int j = 0; j < 6; j++) {
            float4 ea  = __ldcs(&ra[j * 32 + lane]);
            float4 eb4 = __ldcs(&rb[j * 32 + lane]);
            float4 ww  = wv[j * 32 + lane];
            acc_a += ea.x * ww.x + ea.y * ww.y + ea.z * ww.z + ea.w * ww.w;
            acc_b += eb4.x* ww.x + eb4.y* ww.y + eb4.z* ww.z + eb4.w* ww.w;
        }
        #pragma unroll
        for (int off = 16; off; off >>= 1) {
            acc_a += __shfl_xor_sync(0xFFFFFFFFu, acc_a, off);
            acc_b += __shfl_xor_sync(0xFFFFFFFFu, acc_b, off);
        }
        if (lane == 0) {
            float sa = acc_a + bval;
            float sb = acc_b + bval;
            if (mask[(size_t)b * Kv + ka] == 0) sa = NEG_INF;
            if (mask[(size_t)b * Kv + kb] == 0) sb = NEG_INF;
            g_scores[(size_t)b * Kv + ka] = sa;
            g_scores[(size_t)b * Kv + kb] = sb;
        }
    }
}

// ---------------- K2: warp-register top-k + vectorized pooling ----------------
__global__ __launch_bounds__(T2)
void topk_pool_kernel(const float* __restrict__ emb,
                      const int*   __restrict__ topk,
                      float*       __restrict__ out)
{
    __shared__ int s_top[MAX_TOPK];

    const int b    = blockIdx.x;
    const int tid  = threadIdx.x;
    const int lane = tid & 31;
    const int wid  = tid >> 5;

    int ksel = topk[0];
    if (ksel > Kv) ksel = Kv;
    if (ksel < 1)  ksel = 1;
    if (ksel > MAX_TOPK) ksel = MAX_TOPK;

    float* out_pool = out;                      // (B, D)
    float* out_attn = out + (size_t)Bv * Dv;    // (B, K)

    if (wid == 0) {
        // lane holds scores at indices lane + 32*j, j = 0..15 (coalesced L2 loads)
        float v[16];
        const float* sc = g_scores + (size_t)b * Kv;
        #pragma unroll
        for (int j = 0; j < 16; j++) v[j] = sc[lane + 32 * j];

        // ksel argmax rounds, warp-only (no block barriers)
        for (int m = 0; m < ksel; m++) {
            float bv = v[0]; int bj = 0;
            #pragma unroll
            for (int j = 1; j < 16; j++)
                if (v[j] > bv) { bv = v[j]; bj = j; }   // ties: keep lowest j
            int bidx = lane + 32 * bj;
            #pragma unroll
            for (int off = 16; off; off >>= 1) {
                float v2 = __shfl_xor_sync(0xFFFFFFFFu, bv, off);
                int   i2 = __shfl_xor_sync(0xFFFFFFFFu, bidx, off);
                if (v2 > bv || (v2 == bv && i2 < bidx)) { bv = v2; bidx = i2; }
            }
            // all lanes agree on winner; owning lane knocks it out
            if (lane == (bidx & 31)) v[bidx >> 5] = SENTINEL;
            if (lane == 0) s_top[m] = bidx;
        }
    } else {
        // warps 1..7 zero this row's attn weights concurrently (d_out is poisoned)
        for (int i = tid - 32; i < Kv; i += T2 - 32)
            out_attn[(size_t)b * Kv + i] = 0.f;
    }
    __syncthreads();

    const float inv = 1.f / (float)ksel;
    if (tid < ksel)
        out_attn[(size_t)b * Kv + s_top[tid]] = inv;

    // pooling: 192 threads, one float4 column each, ksel independent loads
    if (tid < D4) {
        const float4* ebv = (const float4*)(emb + (size_t)b * Kv * Dv);
        float4 sum = make_float4(0.f, 0.f, 0.f, 0.f);
        if (ksel == 8) {
            int t[8];
            #pragma unroll
            for (int m = 0; m < 8; m++) t[m] = s_top[m];
            #pragma unroll
            for (int m = 0; m < 8; m++) {
                float4 e = __ldg(&ebv[(size_t)t[m] * D4 + tid]);
                sum.x += e.x; sum.y += e.y; sum.z += e.z; sum.w += e.w;
            }
        } else {
            #pragma unroll 4
            for (int m = 0; m < ksel; m++) {
                float4 e = __ldg(&ebv[(size_t)s_top[m] * D4 + tid]);
                sum.x += e.x; sum.y += e.y; sum.z += e.z; sum.w += e.w;
            }
        }
        float4 r = make_float4(sum.x * inv, sum.y * inv, sum.z * inv, sum.w * inv);
        ((float4*)(out_pool + (size_t)b * Dv))[tid] = r;
    }
}

extern "C" void kernel_launch(void* const* d_in, const int* in_sizes, int n_in,
                              void* d_out, int out_size)
{
    const float* emb  = (const float*)d_in[0];
    const int*   mask = (const int*)  d_in[1];
    const float* w    = (const float*)d_in[2];
    const float* bias = (const float*)d_in[3];
    const int*   topk = (const int*)  d_in[4];
    float*       out  = (float*)d_out;
    (void)in_sizes; (void)n_in; (void)out_size;

    score_kernel<<<Bv * SPLIT, T1>>>(emb, mask, w, bias);
    topk_pool_kernel<<<Bv, T2>>>(emb, topk, out);
}